// round 1
// baseline (speedup 1.0000x reference)
#include <cuda_runtime.h>

#define MAXN  100000
#define MAXE  600000
#define NG    512
#define H     128
#define NVOC  4096

// ---- scratch (static __device__ globals; allocation-free) ----
__device__ int   g_deg[MAXN];
__device__ int   g_cursor[MAXN];
__device__ int   g_rowptr[MAXN + 1];
__device__ int   g_csr[MAXE];
__device__ float g_dis[MAXN];
__device__ float g_embW1[NVOC * H];          // 2 MB
__device__ float g_h1[(size_t)MAXN * H];     // 51.2 MB
__device__ float g_gsum[NG * H];
__device__ int   g_gcnt[NG];
__device__ int   g_bsum[1024];

// ---- zero the per-replay accumulators ----
__global__ void k_zero(int N) {
    int i = blockIdx.x * blockDim.x + threadIdx.x;
    int stride = gridDim.x * blockDim.x;
    for (int t = i; t < N; t += stride) { g_deg[t] = 0; g_cursor[t] = 0; }
    for (int t = i; t < NG * H; t += stride) g_gsum[t] = 0.f;
    for (int t = i; t < NG; t += stride) g_gcnt[t] = 0;
}

// ---- in-degree count + per-graph node count (smem histogram) ----
__global__ void k_count(const int* __restrict__ dst, int E,
                        const int* __restrict__ batch, int N) {
    __shared__ int hist[NG];
    for (int i = threadIdx.x; i < NG; i += blockDim.x) hist[i] = 0;
    __syncthreads();
    int i0 = blockIdx.x * blockDim.x + threadIdx.x;
    int stride = gridDim.x * blockDim.x;
    for (int e = i0; e < E; e += stride) atomicAdd(&g_deg[dst[e]], 1);
    for (int v = i0; v < N; v += stride) atomicAdd(&hist[batch[v]], 1);
    __syncthreads();
    for (int i = threadIdx.x; i < NG; i += blockDim.x)
        if (hist[i]) atomicAdd(&g_gcnt[i], hist[i]);
}

// ---- 3-phase exclusive scan of g_deg -> g_rowptr ----
__global__ void k_scanA(int N) {
    __shared__ int s[1024];
    int i = blockIdx.x * 1024 + threadIdx.x;
    int v = (i < N) ? g_deg[i] : 0;
    s[threadIdx.x] = v;
    __syncthreads();
    for (int off = 512; off > 0; off >>= 1) {
        if (threadIdx.x < off) s[threadIdx.x] += s[threadIdx.x + off];
        __syncthreads();
    }
    if (threadIdx.x == 0) g_bsum[blockIdx.x] = s[0];
}

__global__ void k_scanB(int nb) {
    if (threadIdx.x == 0) {
        int acc = 0;
        for (int b = 0; b < nb; b++) { int t = g_bsum[b]; g_bsum[b] = acc; acc += t; }
    }
}

__global__ void k_scanC(int N, int E) {
    __shared__ int s[1024];
    int i = blockIdx.x * 1024 + threadIdx.x;
    int v = (i < N) ? g_deg[i] : 0;
    s[threadIdx.x] = v;
    __syncthreads();
    for (int off = 1; off < 1024; off <<= 1) {
        int u = (threadIdx.x >= (unsigned)off) ? s[threadIdx.x - off] : 0;
        __syncthreads();
        s[threadIdx.x] += u;
        __syncthreads();
    }
    if (i < N) {
        g_rowptr[i] = s[threadIdx.x] - v + g_bsum[blockIdx.x];
        g_dis[i] = rsqrtf((float)(v + 1));   // +1 self-loop; deg>=1 always
    }
    if (i == 0) g_rowptr[N] = E;
}

// ---- fill CSR (src lists grouped by dst) ----
__global__ void k_fill(const int* __restrict__ src, const int* __restrict__ dst, int E) {
    int i0 = blockIdx.x * blockDim.x + threadIdx.x;
    int stride = gridDim.x * blockDim.x;
    for (int e = i0; e < E; e += stride) {
        int d = dst[e];
        int pos = atomicAdd(&g_cursor[d], 1);
        g_csr[g_rowptr[d] + pos] = src[e];
    }
}

// ---- embW1 = emb @ W1  (4096x128x128) ----
__global__ void k_embW1(const float* __restrict__ emb, const float* __restrict__ W1) {
    int j = threadIdx.x;                 // 0..127 (output col)
    int r0 = blockIdx.x * 32;
    for (int r = r0; r < r0 + 32; r++) {
        const float* er = emb + (size_t)r * H;
        float acc = 0.f;
#pragma unroll 8
        for (int k = 0; k < H; k++) acc = fmaf(__ldg(er + k), W1[k * H + j], acc);
        g_embW1[(size_t)r * H + j] = acc;
    }
}

// ---- conv1: h1[v] = relu(b1 + sum_{s->v} dis[s]dis[v]*embW1[x[s]] + dis[v]^2*embW1[x[v]]) ----
__global__ void k_conv1(const int* __restrict__ x, const float* __restrict__ b1, int N) {
    int gw = (blockIdx.x * blockDim.x + threadIdx.x) >> 5;
    int lane = threadIdx.x & 31;
    if (gw >= N) return;
    int v = gw;
    float dv = g_dis[v];
    const float4* T = (const float4*)g_embW1;

    float4 r = T[(size_t)__ldg(x + v) * 32 + lane];
    float w = dv * dv;
    float ax = w * r.x, ay = w * r.y, az = w * r.z, aw = w * r.w;

    int e0 = g_rowptr[v], e1 = g_rowptr[v + 1];
    for (int e = e0; e < e1; e++) {
        int s = g_csr[e];
        float ws = dv * g_dis[s];
        float4 rr = T[(size_t)__ldg(x + s) * 32 + lane];
        ax = fmaf(ws, rr.x, ax); ay = fmaf(ws, rr.y, ay);
        az = fmaf(ws, rr.z, az); aw = fmaf(ws, rr.w, aw);
    }
    float4 bb = ((const float4*)b1)[lane];
    float4 o;
    o.x = fmaxf(ax + bb.x, 0.f); o.y = fmaxf(ay + bb.y, 0.f);
    o.z = fmaxf(az + bb.z, 0.f); o.w = fmaxf(aw + bb.w, 0.f);
    ((float4*)g_h1)[(size_t)v * 32 + lane] = o;
}

// ---- conv2 scatter fused with graph pooling (batch is sorted) ----
__global__ void k_conv2pool(const int* __restrict__ batch, int N) {
    const int NPW = 16;
    int gw = (blockIdx.x * blockDim.x + threadIdx.x) >> 5;
    int lane = threadIdx.x & 31;
    int v0 = gw * NPW;
    if (v0 >= N) return;
    int v1 = min(v0 + NPW, N);
    const float4* Hm = (const float4*)g_h1;

    float gx = 0.f, gy = 0.f, gz = 0.f, gwv = 0.f;
    int curg = -1;
    for (int v = v0; v < v1; v++) {
        float dv = g_dis[v];
        float4 r = Hm[(size_t)v * 32 + lane];
        float w = dv * dv;
        float nx = w * r.x, ny = w * r.y, nz = w * r.z, nw = w * r.w;
        int e0 = g_rowptr[v], e1 = g_rowptr[v + 1];
        for (int e = e0; e < e1; e++) {
            int s = g_csr[e];
            float ws = dv * g_dis[s];
            float4 rr = Hm[(size_t)s * 32 + lane];
            nx = fmaf(ws, rr.x, nx); ny = fmaf(ws, rr.y, ny);
            nz = fmaf(ws, rr.z, nz); nw = fmaf(ws, rr.w, nw);
        }
        int g = batch[v];
        if (g != curg) {
            if (curg >= 0) {
                float* p = g_gsum + curg * H + lane * 4;
                atomicAdd(p, gx); atomicAdd(p + 1, gy);
                atomicAdd(p + 2, gz); atomicAdd(p + 3, gwv);
            }
            curg = g; gx = nx; gy = ny; gz = nz; gwv = nw;
        } else {
            gx += nx; gy += ny; gz += nz; gwv += nw;
        }
    }
    if (curg >= 0) {
        float* p = g_gsum + curg * H + lane * 4;
        atomicAdd(p, gx); atomicAdd(p + 1, gy);
        atomicAdd(p + 2, gz); atomicAdd(p + 3, gwv);
    }
}

// ---- final: out[g] = (gsum[g] @ W2) / cnt[g] + b2  (512x128x128) ----
__global__ void k_final(const float* __restrict__ W2, const float* __restrict__ b2,
                        float* __restrict__ out) {
    __shared__ float srow[H];
    int g = blockIdx.x, j = threadIdx.x;
    srow[j] = g_gsum[g * H + j];
    __syncthreads();
    float acc = 0.f;
#pragma unroll 8
    for (int k = 0; k < H; k++) acc = fmaf(srow[k], W2[k * H + j], acc);
    float c = (float)max(g_gcnt[g], 1);
    out[g * H + j] = acc / c + b2[j];
}

extern "C" void kernel_launch(void* const* d_in, const int* in_sizes, int n_in,
                              void* d_out, int out_size) {
    const int*   x     = (const int*)d_in[0];
    const int*   ei    = (const int*)d_in[1];
    const int*   batch = (const int*)d_in[2];
    const float* emb   = (const float*)d_in[3];
    const float* W1    = (const float*)d_in[4];
    const float* b1    = (const float*)d_in[5];
    const float* W2    = (const float*)d_in[6];
    const float* b2    = (const float*)d_in[7];
    float* out = (float*)d_out;

    int N = in_sizes[0];
    int E = in_sizes[1] / 2;
    const int* src = ei;
    const int* dst = ei + E;

    k_zero<<<256, 256>>>(N);
    k_count<<<512, 256>>>(dst, E, batch, N);
    int nb = (N + 1023) / 1024;
    k_scanA<<<nb, 1024>>>(N);
    k_scanB<<<1, 32>>>(nb);
    k_scanC<<<nb, 1024>>>(N, E);
    k_fill<<<(E + 255) / 256, 256>>>(src, dst, E);
    k_embW1<<<NVOC / 32, H>>>(emb, W1);
    k_conv1<<<(N * 32 + 255) / 256, 256>>>(x, b1, N);
    int warps2 = (N + 15) / 16;
    k_conv2pool<<<(warps2 * 32 + 255) / 256, 256>>>(batch, N);
    k_final<<<NG, H>>>(W2, b2, out);
}

// round 4
// speedup vs baseline: 1.2232x; 1.2232x over previous
#include <cuda_runtime.h>
#include <cuda_fp16.h>

#define MAXN  100000
#define MAXE  600000
#define NG    512
#define H     128
#define NVOC  4096

// ---- scratch (static __device__ globals; allocation-free) ----
__device__ int   g_deg[MAXN];
__device__ int   g_cursor[MAXN];
__device__ int   g_rowptr[MAXN + 1];
__device__ int   g_csr[MAXE];     // src node id per edge (grouped by dst)
__device__ int   g_csrx[MAXE];    // x[src] per edge
__device__ float g_csrw[MAXE];    // dis[src] per edge
__device__ float g_dis[MAXN];
__device__ uint2 g_embW1h[NVOC * H / 4];          // fp16 table, 1 MB
__device__ uint2 g_h1h[(size_t)MAXN * H / 4];     // fp16 h1, 25.6 MB
__device__ float g_gsum[NG * H];
__device__ int   g_gcnt[NG];
__device__ int   g_bsum[128];

// ---- fused: embW1 = emb @ W1 (fp16 out)  +  zero accumulators ----
__global__ void k_prep(const float* __restrict__ emb, const float* __restrict__ W1, int N) {
    int b = blockIdx.x;
    if (b < 128) {
        // GEMM part: 32 rows per block, 128 cols (one per thread)
        int j = threadIdx.x;
        int r0 = b * 32;
        __half* T = (__half*)g_embW1h;
        for (int r = r0; r < r0 + 32; r++) {
            const float* er = emb + (size_t)r * H;
            float acc = 0.f;
#pragma unroll 8
            for (int k = 0; k < H; k++) acc = fmaf(__ldg(er + k), W1[k * H + j], acc);
            T[(size_t)r * H + j] = __float2half_rn(acc);
        }
    } else {
        // zero part: 128 blocks x 128 threads
        int i = (b - 128) * blockDim.x + threadIdx.x;
        int stride = 128 * blockDim.x;
        for (int t = i; t < N; t += stride) { g_deg[t] = 0; g_cursor[t] = 0; }
        for (int t = i; t < NG * H; t += stride) g_gsum[t] = 0.f;
        for (int t = i; t < NG; t += stride) g_gcnt[t] = 0;
    }
}

// ---- in-degree count + per-graph node count ----
__global__ void k_count(const int* __restrict__ dst, int E,
                        const int* __restrict__ batch, int N) {
    __shared__ int hist[NG];
    for (int i = threadIdx.x; i < NG; i += blockDim.x) hist[i] = 0;
    __syncthreads();
    int i0 = blockIdx.x * blockDim.x + threadIdx.x;
    int stride = gridDim.x * blockDim.x;
    for (int e = i0; e < E; e += stride) atomicAdd(&g_deg[dst[e]], 1);
    for (int v = i0; v < N; v += stride) atomicAdd(&hist[batch[v]], 1);
    __syncthreads();
    for (int i = threadIdx.x; i < NG; i += blockDim.x)
        if (hist[i]) atomicAdd(&g_gcnt[i], hist[i]);
}

// ---- 3-phase exclusive scan of g_deg -> g_rowptr ----
__global__ void k_scanA(int N) {
    __shared__ int s[1024];
    int i = blockIdx.x * 1024 + threadIdx.x;
    int v = (i < N) ? g_deg[i] : 0;
    s[threadIdx.x] = v;
    __syncthreads();
    for (int off = 512; off > 0; off >>= 1) {
        if (threadIdx.x < off) s[threadIdx.x] += s[threadIdx.x + off];
        __syncthreads();
    }
    if (threadIdx.x == 0) g_bsum[blockIdx.x] = s[0];
}

__global__ void k_scanB(int nb) {
    __shared__ int s[128];
    int t = threadIdx.x;
    int v = (t < nb && t < 128) ? g_bsum[t] : 0;
    s[t] = v;
    __syncthreads();
    for (int off = 1; off < 128; off <<= 1) {
        int u = (t >= off) ? s[t - off] : 0;
        __syncthreads();
        s[t] += u;
        __syncthreads();
    }
    if (t < nb && t < 128) g_bsum[t] = s[t] - v;   // exclusive
}

__global__ void k_scanC(int N, int E) {
    __shared__ int s[1024];
    int i = blockIdx.x * 1024 + threadIdx.x;
    int v = (i < N) ? g_deg[i] : 0;
    s[threadIdx.x] = v;
    __syncthreads();
    for (int off = 1; off < 1024; off <<= 1) {
        int u = (threadIdx.x >= (unsigned)off) ? s[threadIdx.x - off] : 0;
        __syncthreads();
        s[threadIdx.x] += u;
        __syncthreads();
    }
    if (i < N) {
        g_rowptr[i] = s[threadIdx.x] - v + g_bsum[blockIdx.x];
        g_dis[i] = rsqrtf((float)(v + 1));   // +1 self-loop
    }
    if (i == 0) g_rowptr[N] = E;
}

// ---- fill CSR + per-edge precompute of x[src], dis[src] ----
__global__ void k_fill(const int* __restrict__ src, const int* __restrict__ dst,
                       const int* __restrict__ x, int E) {
    int i0 = blockIdx.x * blockDim.x + threadIdx.x;
    int stride = gridDim.x * blockDim.x;
    for (int e = i0; e < E; e += stride) {
        int d = dst[e];
        int s = src[e];
        int pos = atomicAdd(&g_cursor[d], 1);
        int idx = g_rowptr[d] + pos;
        g_csr[idx]  = s;
        g_csrx[idx] = x[s];
        g_csrw[idx] = g_dis[s];
    }
}

__device__ __forceinline__ void fma_row(uint2 u, float w,
                                        float& ax, float& ay, float& az, float& aw) {
    float2 f0 = __half22float2(*(__half2*)&u.x);
    float2 f1 = __half22float2(*(__half2*)&u.y);
    ax = fmaf(w, f0.x, ax); ay = fmaf(w, f0.y, ay);
    az = fmaf(w, f1.x, az); aw = fmaf(w, f1.y, aw);
}

// ---- conv1: h1[v] = relu(b1 + sum_edges + self) ----
__global__ void k_conv1(const int* __restrict__ x, const float* __restrict__ b1, int N) {
    int v = (blockIdx.x * blockDim.x + threadIdx.x) >> 5;
    int lane = threadIdx.x & 31;
    if (v >= N) return;
    float dv = g_dis[v];
    const uint2* T = (const uint2*)g_embW1h;

    uint2 us = __ldg(&T[(size_t)__ldg(x + v) * 32 + lane]);
    float ax = 0.f, ay = 0.f, az = 0.f, aw = 0.f;
    fma_row(us, dv * dv, ax, ay, az, aw);

    int e = g_rowptr[v], e1 = g_rowptr[v + 1];
    for (; e + 1 < e1; e += 2) {
        int x0 = g_csrx[e], x1 = g_csrx[e + 1];
        float w0 = dv * g_csrw[e], w1 = dv * g_csrw[e + 1];
        uint2 u0 = __ldg(&T[(size_t)x0 * 32 + lane]);
        uint2 u1 = __ldg(&T[(size_t)x1 * 32 + lane]);
        fma_row(u0, w0, ax, ay, az, aw);
        fma_row(u1, w1, ax, ay, az, aw);
    }
    if (e < e1) {
        int x0 = g_csrx[e];
        float w0 = dv * g_csrw[e];
        uint2 u0 = __ldg(&T[(size_t)x0 * 32 + lane]);
        fma_row(u0, w0, ax, ay, az, aw);
    }
    float4 bb = ((const float4*)b1)[lane];
    float ox = fmaxf(ax + bb.x, 0.f), oy = fmaxf(ay + bb.y, 0.f);
    float oz = fmaxf(az + bb.z, 0.f), ow = fmaxf(aw + bb.w, 0.f);
    __half2 p0 = __floats2half2_rn(ox, oy);
    __half2 p1 = __floats2half2_rn(oz, ow);
    uint2 o;
    o.x = *(unsigned*)&p0; o.y = *(unsigned*)&p1;
    g_h1h[(size_t)v * 32 + lane] = o;
}

// ---- conv2 scatter fused with graph pooling (batch is sorted) ----
__global__ void k_conv2pool(const int* __restrict__ batch, int N) {
    const int NPW = 4;
    int gw = (blockIdx.x * blockDim.x + threadIdx.x) >> 5;
    int lane = threadIdx.x & 31;
    int v0 = gw * NPW;
    if (v0 >= N) return;
    int v1 = min(v0 + NPW, N);
    const uint2* Hm = g_h1h;

    float gx = 0.f, gy = 0.f, gz = 0.f, gwv = 0.f;
    int curg = -1;
    for (int v = v0; v < v1; v++) {
        float dv = g_dis[v];
        float nx = 0.f, ny = 0.f, nz = 0.f, nw = 0.f;
        uint2 us = __ldg(&Hm[(size_t)v * 32 + lane]);
        fma_row(us, dv * dv, nx, ny, nz, nw);
        int e = g_rowptr[v], e1 = g_rowptr[v + 1];
        for (; e + 1 < e1; e += 2) {
            int s0 = g_csr[e], s1 = g_csr[e + 1];
            float w0 = dv * g_csrw[e], w1 = dv * g_csrw[e + 1];
            uint2 u0 = __ldg(&Hm[(size_t)s0 * 32 + lane]);
            uint2 u1 = __ldg(&Hm[(size_t)s1 * 32 + lane]);
            fma_row(u0, w0, nx, ny, nz, nw);
            fma_row(u1, w1, nx, ny, nz, nw);
        }
        if (e < e1) {
            int s0 = g_csr[e];
            float w0 = dv * g_csrw[e];
            uint2 u0 = __ldg(&Hm[(size_t)s0 * 32 + lane]);
            fma_row(u0, w0, nx, ny, nz, nw);
        }
        int g = batch[v];
        if (g != curg) {
            if (curg >= 0) {
                float* p = g_gsum + curg * H + lane * 4;
                atomicAdd(p, gx); atomicAdd(p + 1, gy);
                atomicAdd(p + 2, gz); atomicAdd(p + 3, gwv);
            }
            curg = g; gx = nx; gy = ny; gz = nz; gwv = nw;
        } else {
            gx += nx; gy += ny; gz += nz; gwv += nw;
        }
    }
    if (curg >= 0) {
        float* p = g_gsum + curg * H + lane * 4;
        atomicAdd(p, gx); atomicAdd(p + 1, gy);
        atomicAdd(p + 2, gz); atomicAdd(p + 3, gwv);
    }
}

// ---- final: out[g] = (gsum[g] @ W2) / cnt[g] + b2 ----
__global__ void k_final(const float* __restrict__ W2, const float* __restrict__ b2,
                        float* __restrict__ out) {
    __shared__ float srow[H];
    int g = blockIdx.x, j = threadIdx.x;
    srow[j] = g_gsum[g * H + j];
    __syncthreads();
    float acc = 0.f;
#pragma unroll 8
    for (int k = 0; k < H; k++) acc = fmaf(srow[k], W2[k * H + j], acc);
    float c = (float)max(g_gcnt[g], 1);
    out[g * H + j] = acc / c + b2[j];
}

extern "C" void kernel_launch(void* const* d_in, const int* in_sizes, int n_in,
                              void* d_out, int out_size) {
    const int*   x     = (const int*)d_in[0];
    const int*   ei    = (const int*)d_in[1];
    const int*   batch = (const int*)d_in[2];
    const float* emb   = (const float*)d_in[3];
    const float* W1    = (const float*)d_in[4];
    const float* b1    = (const float*)d_in[5];
    const float* W2    = (const float*)d_in[6];
    const float* b2    = (const float*)d_in[7];
    float* out = (float*)d_out;

    int N = in_sizes[0];
    int E = in_sizes[1] / 2;
    const int* src = ei;
    const int* dst = ei + E;

    k_prep<<<256, 128>>>(emb, W1, N);
    k_count<<<512, 256>>>(dst, E, batch, N);
    int nb = (N + 1023) / 1024;
    k_scanA<<<nb, 1024>>>(N);
    k_scanB<<<1, 128>>>(nb);
    k_scanC<<<nb, 1024>>>(N, E);
    k_fill<<<(E + 255) / 256, 256>>>(src, dst, x, E);
    k_conv1<<<((size_t)N * 32 + 255) / 256, 256>>>(x, b1, N);
    int warps2 = (N + 3) / 4;
    k_conv2pool<<<((size_t)warps2 * 32 + 255) / 256, 256>>>(batch, N);
    k_final<<<NG, H>>>(W2, b2, out);
}